// round 1
// baseline (speedup 1.0000x reference)
#include <cuda_runtime.h>
#include <math.h>

#define B_SZ    8
#define L_SEQ   1024
#define ENC_IN  32
#define D_MODEL 256
#define D_INNER 512
#define D_STATE 16
#define D_CONV  4
#define DT_RANK 16
#define N_LAYERS 2
#define D_FF    1024
#define MROWS   (B_SZ * L_SEQ)   // 8192
#define XDBL_W  (DT_RANK + 2 * D_STATE)   // 48

// ---------------- scratch (static device globals; no allocs allowed) -------
__device__ float g_h   [MROWS * D_MODEL];          //  8.4 MB
__device__ float g_xz  [MROWS * 2 * D_INNER];      // 33.6 MB
__device__ float g_xc  [MROWS * D_INNER];          // 16.8 MB
__device__ float g_xdbl[MROWS * XDBL_W];           //  1.6 MB
__device__ float g_dt  [MROWS * D_INNER];          // 16.8 MB
__device__ float g_y   [MROWS * D_INNER];          // 16.8 MB
__device__ float g_fc  [B_SZ * D_FF];

// ---------------------------------------------------------------------------
// Generic fp32 GEMM:  C[M,N] = A[M,K] (lda) @ W[N,K]^T   (+bias, +softplus)
// BM=BN=128, BK=8, 256 threads, 8x8 register tile per thread.
// M is gridDim.x*128 (always multiple of 128 here); N guarded.
// epi: 0 = none, 1 = +bias, 2 = softplus(+bias)
// ---------------------------------------------------------------------------
__global__ void __launch_bounds__(256) gemm_f32(
    const float* __restrict__ A, const float* __restrict__ W,
    const float* __restrict__ bias, float* __restrict__ C,
    int N, int K, int lda, int epi)
{
    __shared__ float As[8][128];
    __shared__ float Ws[8][128];

    const int tid = threadIdx.x;
    const int m0 = blockIdx.x * 128;
    const int n0 = blockIdx.y * 128;
    const int ty = tid >> 4;          // 0..15
    const int tx = tid & 15;          // 0..15

    float acc[8][8];
#pragma unroll
    for (int i = 0; i < 8; i++)
#pragma unroll
        for (int j = 0; j < 8; j++) acc[i][j] = 0.f;

    const int lrow = tid >> 1;        // 0..127
    const int lk   = (tid & 1) * 4;   // 0 or 4
    const float* Aptr = A + (size_t)(m0 + lrow) * lda + lk;
    const int nrow = n0 + lrow;
    const float* Wptr = W + (size_t)nrow * K + lk;
    const bool wok = (nrow < N);

    for (int k0 = 0; k0 < K; k0 += 8) {
        float4 av = *(const float4*)(Aptr + k0);
        float4 wv = make_float4(0.f, 0.f, 0.f, 0.f);
        if (wok) wv = *(const float4*)(Wptr + k0);

        __syncthreads();
        As[lk + 0][lrow] = av.x; As[lk + 1][lrow] = av.y;
        As[lk + 2][lrow] = av.z; As[lk + 3][lrow] = av.w;
        Ws[lk + 0][lrow] = wv.x; Ws[lk + 1][lrow] = wv.y;
        Ws[lk + 2][lrow] = wv.z; Ws[lk + 3][lrow] = wv.w;
        __syncthreads();

#pragma unroll
        for (int k = 0; k < 8; k++) {
            float a[8], w[8];
#pragma unroll
            for (int i = 0; i < 8; i++) a[i] = As[k][ty * 8 + i];
#pragma unroll
            for (int j = 0; j < 8; j++) w[j] = Ws[k][tx * 8 + j];
#pragma unroll
            for (int i = 0; i < 8; i++)
#pragma unroll
                for (int j = 0; j < 8; j++)
                    acc[i][j] = fmaf(a[i], w[j], acc[i][j]);
        }
    }

#pragma unroll
    for (int j = 0; j < 8; j++) {
        const int n = n0 + tx * 8 + j;
        if (n >= N) continue;
        const float bv = (epi >= 1) ? bias[n] : 0.f;
#pragma unroll
        for (int i = 0; i < 8; i++) {
            float v = acc[i][j] + bv;
            if (epi == 2) v = (v > 20.f) ? v : log1pf(__expf(v));
            C[(size_t)(m0 + ty * 8 + i) * N + n] = v;
        }
    }
}

// ---------------------------------------------------------------------------
// Fused causal depthwise conv (width 4) + bias + SiLU.
// xi = xz[:, :, 0:512] ; writes xc[b,l,d].
// ---------------------------------------------------------------------------
__global__ void conv_silu_kernel(const float* __restrict__ xz,
                                 const float* __restrict__ cw,  // [512,4]
                                 const float* __restrict__ cb,  // [512]
                                 float* __restrict__ xc)
{
    int idx = blockIdx.x * blockDim.x + threadIdx.x;
    if (idx >= MROWS * D_INNER) return;
    const int d  = idx & (D_INNER - 1);
    const int bl = idx >> 9;                 // b*L + l
    const int l  = bl & (L_SEQ - 1);

    const float w0 = cw[d * 4 + 0], w1 = cw[d * 4 + 1];
    const float w2 = cw[d * 4 + 2], w3 = cw[d * 4 + 3];
    const float* base = xz + (size_t)bl * (2 * D_INNER) + d;
    const int stride = 2 * D_INNER;

    float acc = cb[d];
    acc = fmaf(base[0], w3, acc);
    if (l >= 1) acc = fmaf(base[-1 * stride], w2, acc);
    if (l >= 2) acc = fmaf(base[-2 * stride], w1, acc);
    if (l >= 3) acc = fmaf(base[-3 * stride], w0, acc);

    xc[idx] = acc / (1.f + __expf(-acc));   // silu
}

// ---------------------------------------------------------------------------
// Selective scan, fused with D-skip and z-gate (silu).
// 16 lanes per (b,d) channel: lane holds h[n]; 2 channels per warp.
// Butterfly-reduce y = sum_n h*C (does not feed the recurrence -> pipelines).
// ---------------------------------------------------------------------------
__global__ void __launch_bounds__(256) scan_kernel(
    const float* __restrict__ dtbuf,   // [MROWS,512]
    const float* __restrict__ xc,      // u, [MROWS,512]
    const float* __restrict__ xdbl,    // [MROWS,48] (B at 16.., C at 32..)
    const float* __restrict__ xz,      // z at [.,512+d]
    const float* __restrict__ A_log,   // [512,16] (layer slice)
    const float* __restrict__ Dskip,   // [512]    (layer slice)
    float* __restrict__ y)             // [MROWS,512]
{
    const int warp = (blockIdx.x * blockDim.x + threadIdx.x) >> 5;
    const int lane = threadIdx.x & 31;
    const int grp  = lane >> 4;
    const int n    = lane & 15;
    const int ch   = warp * 2 + grp;        // 0..4095
    const int b    = ch >> 9;
    const int d    = ch & 511;

    const float A  = -__expf(A_log[d * 16 + n]);
    const float Dv = Dskip[d];

    float h = 0.f;
    const size_t bl = (size_t)b * L_SEQ;

    for (int l = 0; l < L_SEQ; l++) {
        const size_t r = bl + l;
        const float dt = dtbuf[r * D_INNER + d];
        const float u  = xc   [r * D_INNER + d];
        const float Bv = xdbl [r * XDBL_W + DT_RANK + n];
        const float Cv = xdbl [r * XDBL_W + DT_RANK + D_STATE + n];

        const float dA = __expf(dt * A);
        h = fmaf(dA, h, dt * Bv * u);

        float p = h * Cv;
        p += __shfl_xor_sync(0xffffffffu, p, 1);
        p += __shfl_xor_sync(0xffffffffu, p, 2);
        p += __shfl_xor_sync(0xffffffffu, p, 4);
        p += __shfl_xor_sync(0xffffffffu, p, 8);

        if (n == 0) {
            const float z  = xz[r * (2 * D_INNER) + D_INNER + d];
            const float sz = z / (1.f + __expf(-z));
            y[r * D_INNER + d] = (p + u * Dv) * sz;
        }
    }
}

// ---------------------------------------------------------------------------
// Head: fc = gelu(h_last @ p1^T + b1);  out = fc @ p2^T + b2
// ---------------------------------------------------------------------------
__global__ void head1_kernel(const float* __restrict__ h,
                             const float* __restrict__ p1w,
                             const float* __restrict__ p1b,
                             float* __restrict__ fc)
{
    int idx = blockIdx.x * blockDim.x + threadIdx.x;
    if (idx >= B_SZ * D_FF) return;
    const int b = idx / D_FF;
    const int f = idx - b * D_FF;
    const float4* hp = (const float4*)(h + ((size_t)b * L_SEQ + (L_SEQ - 1)) * D_MODEL);
    const float4* wp = (const float4*)(p1w + (size_t)f * D_MODEL);
    float acc = 0.f;
#pragma unroll 8
    for (int k = 0; k < D_MODEL / 4; k++) {
        float4 a = hp[k], w = wp[k];
        acc += a.x * w.x + a.y * w.y + a.z * w.z + a.w * w.w;
    }
    acc += p1b[f];
    fc[idx] = 0.5f * acc * (1.f + erff(acc * 0.70710678118f));   // exact gelu
}

__global__ void head2_kernel(const float* __restrict__ fc,
                             const float* __restrict__ p2w,
                             const float* __restrict__ p2b,
                             float* __restrict__ out)
{
    const int b = blockIdx.x;
    const int t = threadIdx.x;
    float acc = 0.f;
    for (int k = t; k < D_FF; k += 256) acc += fc[b * D_FF + k] * p2w[k];
    __shared__ float s[8];
#pragma unroll
    for (int o = 16; o; o >>= 1) acc += __shfl_xor_sync(0xffffffffu, acc, o);
    if ((t & 31) == 0) s[t >> 5] = acc;
    __syncthreads();
    if (t < 8) {
        float v = s[t];
#pragma unroll
        for (int o = 4; o; o >>= 1) v += __shfl_xor_sync(0x000000ffu, v, o);
        if (t == 0) out[b] = v + p2b[0];
    }
}

// ---------------------------------------------------------------------------
extern "C" void kernel_launch(void* const* d_in, const int* in_sizes, int n_in,
                              void* d_out, int out_size)
{
    (void)in_sizes; (void)n_in; (void)out_size;
    const float* x          = (const float*)d_in[0];
    const float* in_w       = (const float*)d_in[1];
    const float* in_b       = (const float*)d_in[2];
    const float* in_proj_w  = (const float*)d_in[3];
    const float* conv_w     = (const float*)d_in[4];
    const float* conv_b     = (const float*)d_in[5];
    const float* x_proj_w   = (const float*)d_in[6];
    const float* dt_w       = (const float*)d_in[7];
    const float* dt_b       = (const float*)d_in[8];
    const float* A_log      = (const float*)d_in[9];
    const float* D_skip     = (const float*)d_in[10];
    const float* out_proj_w = (const float*)d_in[11];
    const float* p1_w       = (const float*)d_in[12];
    const float* p1_b       = (const float*)d_in[13];
    const float* p2_w       = (const float*)d_in[14];
    const float* p2_b       = (const float*)d_in[15];
    float* out = (float*)d_out;

    float *ph, *pxz, *pxc, *pxdbl, *pdt, *py, *pfc;
    cudaGetSymbolAddress((void**)&ph,    g_h);
    cudaGetSymbolAddress((void**)&pxz,   g_xz);
    cudaGetSymbolAddress((void**)&pxc,   g_xc);
    cudaGetSymbolAddress((void**)&pxdbl, g_xdbl);
    cudaGetSymbolAddress((void**)&pdt,   g_dt);
    cudaGetSymbolAddress((void**)&py,    g_y);
    cudaGetSymbolAddress((void**)&pfc,   g_fc);

    const int MB = MROWS / 128;   // 64 row-blocks

    // h = x @ in_w^T + in_b      [8192,256], K=32
    gemm_f32<<<dim3(MB, D_MODEL / 128), 256>>>(x, in_w, in_b, ph,
                                               D_MODEL, ENC_IN, ENC_IN, 1);

    for (int i = 0; i < N_LAYERS; i++) {
        const float* ipw = in_proj_w  + (size_t)i * 2 * D_INNER * D_MODEL;
        const float* xpw = x_proj_w   + (size_t)i * XDBL_W * D_INNER;
        const float* dtw = dt_w       + (size_t)i * D_INNER * DT_RANK;
        const float* opw = out_proj_w + (size_t)i * D_MODEL * D_INNER;

        // xz = h @ ipw^T          [8192,1024], K=256
        gemm_f32<<<dim3(MB, (2 * D_INNER) / 128), 256>>>(ph, ipw, nullptr, pxz,
                                                         2 * D_INNER, D_MODEL, D_MODEL, 0);
        // xc = silu(dwconv(xi)+b)
        conv_silu_kernel<<<(MROWS * D_INNER) / 256, 256>>>(pxz,
                conv_w + (size_t)i * D_INNER * D_CONV,
                conv_b + (size_t)i * D_INNER, pxc);
        // xdbl = xc @ xpw^T       [8192,48], K=512
        gemm_f32<<<dim3(MB, 1), 256>>>(pxc, xpw, nullptr, pxdbl,
                                       XDBL_W, D_INNER, D_INNER, 0);
        // dt = softplus(xdbl[:, :16] @ dtw^T + dt_b)   [8192,512], K=16
        gemm_f32<<<dim3(MB, D_INNER / 128), 256>>>(pxdbl, dtw,
                                                   dt_b + (size_t)i * D_INNER, pdt,
                                                   D_INNER, DT_RANK, XDBL_W, 2);
        // y = gated selective scan
        scan_kernel<<<(B_SZ * D_INNER / 2) * 32 / 256, 256>>>(pdt, pxc, pxdbl, pxz,
                A_log  + (size_t)i * D_INNER * D_STATE,
                D_skip + (size_t)i * D_INNER, py);
        // h = y @ opw^T           [8192,256], K=512
        gemm_f32<<<dim3(MB, D_MODEL / 128), 256>>>(py, opw, nullptr, ph,
                                                   D_MODEL, D_INNER, D_INNER, 0);
    }

    head1_kernel<<<(B_SZ * D_FF) / 256, 256>>>(ph, p1_w, p1_b, pfc);
    head2_kernel<<<B_SZ, 256>>>(pfc, p2_w, p2_b, out);
}

// round 2
// speedup vs baseline: 1.1662x; 1.1662x over previous
#include <cuda_runtime.h>
#include <math.h>

#define B_SZ    8
#define L_SEQ   1024
#define ENC_IN  32
#define D_MODEL 256
#define D_INNER 512
#define D_STATE 16
#define D_CONV  4
#define DT_RANK 16
#define N_LAYERS 2
#define D_FF    1024
#define MROWS   (B_SZ * L_SEQ)   // 8192
#define XDBL_W  (DT_RANK + 2 * D_STATE)   // 48

typedef unsigned long long ull;

// ---------------- scratch (static device globals; no allocs allowed) -------
__device__ float g_h   [MROWS * D_MODEL];
__device__ float g_xz  [MROWS * 2 * D_INNER];
__device__ float g_xc  [MROWS * D_INNER];
__device__ float g_xdbl[MROWS * XDBL_W];
__device__ float g_dt  [MROWS * D_INNER];
__device__ float g_y   [MROWS * D_INNER];
__device__ float g_fc  [B_SZ * D_FF];

// ---------------- packed f32x2 helpers -------------------------------------
__device__ __forceinline__ ull pk2(float x, float y) {
    ull r;
    asm("mov.b64 %0, {%1, %2};" : "=l"(r) : "f"(x), "f"(y));
    return r;
}
__device__ __forceinline__ void fma2(ull& c, ull a, ull b) {
    asm("fma.rn.f32x2 %0, %1, %2, %0;" : "+l"(c) : "l"(a), "l"(b));
}
__device__ __forceinline__ float2 upk2(ull v) {
    float2 r;
    asm("mov.b64 {%0, %1}, %2;" : "=f"(r.x), "=f"(r.y) : "l"(v));
    return r;
}

// ---------------------------------------------------------------------------
// Templated fp32 GEMM with packed f32x2 FMA:
//   C[M,N](ldc=N) = A[M,K](lda) @ W[N,K]^T   (+bias / +softplus)
// Threads: (BM/TM) x (BN/TN) = TH.  BK=16, register-prefetch pipeline.
// epi: 0 none, 1 +bias, 2 softplus(+bias)
// ---------------------------------------------------------------------------
template<int BM, int BN, int BK, int TM, int TN, int TH>
__global__ void __launch_bounds__(TH) gemm_t(
    const float* __restrict__ A, const float* __restrict__ W,
    const float* __restrict__ bias, float* __restrict__ C,
    int N, int K, int lda, int epi)
{
    constexpr int PAD = 4;
    __shared__ float As[BK][BM + PAD];
    __shared__ float Ws[BK][BN + PAD];
    constexpr int A4 = BM * BK / (TH * 4);   // float4 loads per thread (A)
    constexpr int B4 = BN * BK / (TH * 4);   // float4 loads per thread (W)
    constexpr int KQ = BK / 4;

    const int tid = threadIdx.x;
    const int m0  = blockIdx.x * BM;
    const int n0  = blockIdx.y * BN;
    const int tx  = tid % (BN / TN);
    const int ty  = tid / (BN / TN);

    ull acc[TM][TN / 2];
#pragma unroll
    for (int i = 0; i < TM; i++)
#pragma unroll
        for (int j = 0; j < TN / 2; j++) acc[i][j] = 0ull;

    float4 ar[A4], wr[B4];

#define LOAD_TILES(K0)                                                        \
    {                                                                         \
        _Pragma("unroll")                                                     \
        for (int t = 0; t < A4; t++) {                                        \
            int idx = tid + t * TH;                                           \
            int row = idx / KQ, kq = idx % KQ;                                \
            ar[t] = *(const float4*)(A + (size_t)(m0 + row) * lda + (K0) + kq * 4); \
        }                                                                     \
        _Pragma("unroll")                                                     \
        for (int t = 0; t < B4; t++) {                                        \
            int idx = tid + t * TH;                                           \
            int row = idx / KQ, kq = idx % KQ;                                \
            int n = n0 + row;                                                 \
            wr[t] = (n < N) ? *(const float4*)(W + (size_t)n * K + (K0) + kq * 4) \
                            : make_float4(0.f, 0.f, 0.f, 0.f);                \
        }                                                                     \
    }

    LOAD_TILES(0);

    for (int k0 = 0; k0 < K; k0 += BK) {
        if (k0) __syncthreads();
#pragma unroll
        for (int t = 0; t < A4; t++) {
            int idx = tid + t * TH;
            int row = idx / KQ, kq = idx % KQ;
            As[kq * 4 + 0][row] = ar[t].x;
            As[kq * 4 + 1][row] = ar[t].y;
            As[kq * 4 + 2][row] = ar[t].z;
            As[kq * 4 + 3][row] = ar[t].w;
        }
#pragma unroll
        for (int t = 0; t < B4; t++) {
            int idx = tid + t * TH;
            int row = idx / KQ, kq = idx % KQ;
            Ws[kq * 4 + 0][row] = wr[t].x;
            Ws[kq * 4 + 1][row] = wr[t].y;
            Ws[kq * 4 + 2][row] = wr[t].z;
            Ws[kq * 4 + 3][row] = wr[t].w;
        }
        __syncthreads();
        if (k0 + BK < K) LOAD_TILES(k0 + BK);

#pragma unroll
        for (int k = 0; k < BK; k++) {
            float a[TM], w[TN];
#pragma unroll
            for (int q = 0; q < TM / 4; q++)
                *(float4*)&a[q * 4] = *(const float4*)&As[k][ty * TM + q * 4];
#pragma unroll
            for (int q = 0; q < TN / 4; q++)
                *(float4*)&w[q * 4] = *(const float4*)&Ws[k][tx * TN + q * 4];

            ull w2[TN / 2];
#pragma unroll
            for (int j = 0; j < TN / 2; j++) w2[j] = pk2(w[2 * j], w[2 * j + 1]);
#pragma unroll
            for (int i = 0; i < TM; i++) {
                const ull a2 = pk2(a[i], a[i]);
#pragma unroll
                for (int j = 0; j < TN / 2; j++) fma2(acc[i][j], a2, w2[j]);
            }
        }
    }
#undef LOAD_TILES

#pragma unroll
    for (int i = 0; i < TM; i++) {
        const int m = m0 + ty * TM + i;
#pragma unroll
        for (int j = 0; j < TN / 2; j++) {
            const int n = n0 + tx * TN + 2 * j;
            if (n >= N) continue;
            float2 v = upk2(acc[i][j]);
            if (epi >= 1) { v.x += bias[n]; v.y += bias[n + 1]; }
            if (epi == 2) {
                v.x = (v.x > 20.f) ? v.x : log1pf(__expf(v.x));
                v.y = (v.y > 20.f) ? v.y : log1pf(__expf(v.y));
            }
            *(float2*)&C[(size_t)m * N + n] = v;
        }
    }
}

// ---------------------------------------------------------------------------
// Fused causal depthwise conv (width 4) + bias + SiLU.
// ---------------------------------------------------------------------------
__global__ void conv_silu_kernel(const float* __restrict__ xz,
                                 const float* __restrict__ cw,
                                 const float* __restrict__ cb,
                                 float* __restrict__ xc)
{
    int idx = blockIdx.x * blockDim.x + threadIdx.x;
    if (idx >= MROWS * D_INNER) return;
    const int d  = idx & (D_INNER - 1);
    const int bl = idx >> 9;
    const int l  = bl & (L_SEQ - 1);

    const float w0 = cw[d * 4 + 0], w1 = cw[d * 4 + 1];
    const float w2 = cw[d * 4 + 2], w3 = cw[d * 4 + 3];
    const float* base = xz + (size_t)bl * (2 * D_INNER) + d;
    const int stride = 2 * D_INNER;

    float acc = cb[d];
    acc = fmaf(base[0], w3, acc);
    if (l >= 1) acc = fmaf(base[-1 * stride], w2, acc);
    if (l >= 2) acc = fmaf(base[-2 * stride], w1, acc);
    if (l >= 3) acc = fmaf(base[-3 * stride], w0, acc);

    xc[idx] = acc / (1.f + __expf(-acc));
}

// ---------------------------------------------------------------------------
// Selective scan, fused with D-skip and z-gate (silu).
// ---------------------------------------------------------------------------
__global__ void __launch_bounds__(256) scan_kernel(
    const float* __restrict__ dtbuf,
    const float* __restrict__ xc,
    const float* __restrict__ xdbl,
    const float* __restrict__ xz,
    const float* __restrict__ A_log,
    const float* __restrict__ Dskip,
    float* __restrict__ y)
{
    const int warp = (blockIdx.x * blockDim.x + threadIdx.x) >> 5;
    const int lane = threadIdx.x & 31;
    const int grp  = lane >> 4;
    const int n    = lane & 15;
    const int ch   = warp * 2 + grp;
    const int b    = ch >> 9;
    const int d    = ch & 511;

    const float A  = -__expf(A_log[d * 16 + n]);
    const float Dv = Dskip[d];

    float h = 0.f;
    const size_t bl = (size_t)b * L_SEQ;

    for (int l = 0; l < L_SEQ; l++) {
        const size_t r = bl + l;
        const float dt = dtbuf[r * D_INNER + d];
        const float u  = xc   [r * D_INNER + d];
        const float Bv = xdbl [r * XDBL_W + DT_RANK + n];
        const float Cv = xdbl [r * XDBL_W + DT_RANK + D_STATE + n];

        const float dA = __expf(dt * A);
        h = fmaf(dA, h, dt * Bv * u);

        float p = h * Cv;
        p += __shfl_xor_sync(0xffffffffu, p, 1);
        p += __shfl_xor_sync(0xffffffffu, p, 2);
        p += __shfl_xor_sync(0xffffffffu, p, 4);
        p += __shfl_xor_sync(0xffffffffu, p, 8);

        if (n == 0) {
            const float z  = xz[r * (2 * D_INNER) + D_INNER + d];
            const float sz = z / (1.f + __expf(-z));
            y[r * D_INNER + d] = (p + u * Dv) * sz;
        }
    }
}

// ---------------------------------------------------------------------------
// Head
// ---------------------------------------------------------------------------
__global__ void head1_kernel(const float* __restrict__ h,
                             const float* __restrict__ p1w,
                             const float* __restrict__ p1b,
                             float* __restrict__ fc)
{
    int idx = blockIdx.x * blockDim.x + threadIdx.x;
    if (idx >= B_SZ * D_FF) return;
    const int b = idx / D_FF;
    const int f = idx - b * D_FF;
    const float4* hp = (const float4*)(h + ((size_t)b * L_SEQ + (L_SEQ - 1)) * D_MODEL);
    const float4* wp = (const float4*)(p1w + (size_t)f * D_MODEL);
    float acc = 0.f;
#pragma unroll 8
    for (int k = 0; k < D_MODEL / 4; k++) {
        float4 a = hp[k], w = wp[k];
        acc += a.x * w.x + a.y * w.y + a.z * w.z + a.w * w.w;
    }
    acc += p1b[f];
    fc[idx] = 0.5f * acc * (1.f + erff(acc * 0.70710678118f));
}

__global__ void head2_kernel(const float* __restrict__ fc,
                             const float* __restrict__ p2w,
                             const float* __restrict__ p2b,
                             float* __restrict__ out)
{
    const int b = blockIdx.x;
    const int t = threadIdx.x;
    float acc = 0.f;
    for (int k = t; k < D_FF; k += 256) acc += fc[b * D_FF + k] * p2w[k];
    __shared__ float s[8];
#pragma unroll
    for (int o = 16; o; o >>= 1) acc += __shfl_xor_sync(0xffffffffu, acc, o);
    if ((t & 31) == 0) s[t >> 5] = acc;
    __syncthreads();
    if (t < 8) {
        float v = s[t];
#pragma unroll
        for (int o = 4; o; o >>= 1) v += __shfl_xor_sync(0x000000ffu, v, o);
        if (t == 0) out[b] = v + p2b[0];
    }
}

// ---------------------------------------------------------------------------
extern "C" void kernel_launch(void* const* d_in, const int* in_sizes, int n_in,
                              void* d_out, int out_size)
{
    (void)in_sizes; (void)n_in; (void)out_size;
    const float* x          = (const float*)d_in[0];
    const float* in_w       = (const float*)d_in[1];
    const float* in_b       = (const float*)d_in[2];
    const float* in_proj_w  = (const float*)d_in[3];
    const float* conv_w     = (const float*)d_in[4];
    const float* conv_b     = (const float*)d_in[5];
    const float* x_proj_w   = (const float*)d_in[6];
    const float* dt_w       = (const float*)d_in[7];
    const float* dt_b       = (const float*)d_in[8];
    const float* A_log      = (const float*)d_in[9];
    const float* D_skip     = (const float*)d_in[10];
    const float* out_proj_w = (const float*)d_in[11];
    const float* p1_w       = (const float*)d_in[12];
    const float* p1_b       = (const float*)d_in[13];
    const float* p2_w       = (const float*)d_in[14];
    const float* p2_b       = (const float*)d_in[15];
    float* out = (float*)d_out;

    float *ph, *pxz, *pxc, *pxdbl, *pdt, *py, *pfc;
    cudaGetSymbolAddress((void**)&ph,    g_h);
    cudaGetSymbolAddress((void**)&pxz,   g_xz);
    cudaGetSymbolAddress((void**)&pxc,   g_xc);
    cudaGetSymbolAddress((void**)&pxdbl, g_xdbl);
    cudaGetSymbolAddress((void**)&pdt,   g_dt);
    cudaGetSymbolAddress((void**)&py,    g_y);
    cudaGetSymbolAddress((void**)&pfc,   g_fc);

    // h = x @ in_w^T + in_b   [8192,256], K=32 : 128x64 tiles -> 256 CTAs
    gemm_t<128, 64, 16, 8, 4, 256><<<dim3(MROWS / 128, D_MODEL / 64), 256>>>(
        x, in_w, in_b, ph, D_MODEL, ENC_IN, ENC_IN, 1);

    for (int i = 0; i < N_LAYERS; i++) {
        const float* ipw = in_proj_w  + (size_t)i * 2 * D_INNER * D_MODEL;
        const float* xpw = x_proj_w   + (size_t)i * XDBL_W * D_INNER;
        const float* dtw = dt_w       + (size_t)i * D_INNER * DT_RANK;
        const float* opw = out_proj_w + (size_t)i * D_MODEL * D_INNER;

        // xz = h @ ipw^T   [8192,1024], K=256 : 128x128 -> 512 CTAs
        gemm_t<128, 128, 16, 8, 8, 256><<<dim3(MROWS / 128, (2 * D_INNER) / 128), 256>>>(
            ph, ipw, nullptr, pxz, 2 * D_INNER, D_MODEL, D_MODEL, 0);

        conv_silu_kernel<<<(MROWS * D_INNER) / 256, 256>>>(pxz,
                conv_w + (size_t)i * D_INNER * D_CONV,
                conv_b + (size_t)i * D_INNER, pxc);

        // xdbl = xc @ xpw^T  [8192,48], K=512 : 32x64 tiles -> 256 CTAs
        gemm_t<32, 64, 16, 4, 4, 128><<<dim3(MROWS / 32, 1), 128>>>(
            pxc, xpw, nullptr, pxdbl, XDBL_W, D_INNER, D_INNER, 0);

        // dt = softplus(xdbl[:, :16] @ dtw^T + dt_b)  [8192,512], K=16 -> 512 CTAs
        gemm_t<128, 64, 16, 8, 4, 256><<<dim3(MROWS / 128, D_INNER / 64), 256>>>(
            pxdbl, dtw, dt_b + (size_t)i * D_INNER, pdt, D_INNER, DT_RANK, XDBL_W, 2);

        // y = gated selective scan
        scan_kernel<<<(B_SZ * D_INNER / 2) * 32 / 256, 256>>>(pdt, pxc, pxdbl, pxz,
                A_log  + (size_t)i * D_INNER * D_STATE,
                D_skip + (size_t)i * D_INNER, py);

        // h = y @ opw^T   [8192,256], K=512 : 128x64 -> 256 CTAs
        gemm_t<128, 64, 16, 8, 4, 256><<<dim3(MROWS / 128, D_MODEL / 64), 256>>>(
            py, opw, nullptr, ph, D_MODEL, D_INNER, D_INNER, 0);
    }

    head1_kernel<<<(B_SZ * D_FF) / 256, 256>>>(ph, p1_w, p1_b, pfc);
    head2_kernel<<<B_SZ, 256>>>(pfc, p2_w, p2_b, out);
}